// round 16
// baseline (speedup 1.0000x reference)
#include <cuda_runtime.h>
#include <cstdint>

// delta_layer: out[b,t,:] = [ x, delta(x), delta(delta(x)) ]
// delta(y)[t] = 0.5*(y[c(t+1)]-y[c(t-1)]) + 0.25*(y[c(t+2)]-y[c(t-2)]), c = clamp [0,T-1]
// Shapes fixed: B=32, T=4096, D=256, window=2.
//
// Round-16: persistent-style blocks + DOUBLE-BUFFERED bulk-store epilogue +
// register-ring carry. Grid (41,32)=1312 blocks (~one full wave at 9/SM);
// each block owns ~25 consecutive 4-row tiles of one batch row:
//   - ring warm-up paid once per ~100 rows (read amplification 2.0x -> 1.09x)
//   - two 12KB smem buffers; before writing buffer p, wait_group.read 1
//     (<=1 outstanding) so tile i's store drains while tile i+1 computes
//   - each block writes a contiguous ~300KB output region sequentially
// Interior rows use the fused 9-tap double-delta:
//   dd(t) = 0.0625(x[t-4]+x[t+4]) + 0.25(x[t-3]+x[t+3]) + 0.25(x[t-2]+x[t+2])
//         - 0.25(x[t-1]+x[t+1]) - 0.625 x[t]
// Tiles 0 and 1023 (rows 0-3 and 4092-4095) take the generic clamped path.

#define B_N 32
#define T_N 4096
#define F2_N 128             // float2 per input row (256 floats)
#define OF2_N 384            // float2 per output row (768 floats)
#define TILE_ROWS 4
#define NTILES (T_N / TILE_ROWS)   // 1024
#define SEGS 41                    // segments per batch row -> 41*32 = 1312 blocks
#define TBYTES (TILE_ROWS * OF2_N * 8)   // 12288

__device__ __forceinline__ uint32_t smem_u32(const void* p) {
    uint32_t a;
    asm("{ .reg .u64 t; cvta.to.shared.u64 t, %1; cvt.u32.u64 %0, t; }"
        : "=r"(a) : "l"(p));
    return a;
}

__device__ __forceinline__ float2 f2_delta(float2 m2, float2 m1, float2 p1, float2 p2) {
    float2 r;
    r.x = 0.5f * (p1.x - m1.x) + 0.25f * (p2.x - m2.x);
    r.y = 0.5f * (p1.y - m1.y) + 0.25f * (p2.y - m2.y);
    return r;
}

__device__ __forceinline__ float dd9(float a0, float a1, float a2, float a3, float a4,
                                     float a5, float a6, float a7, float a8) {
    return 0.0625f * (a0 + a8) + 0.25f * (a1 + a7) + 0.25f * (a2 + a6)
         - 0.25f * (a3 + a5) - 0.625f * a4;
}

__global__ void __launch_bounds__(128, 9)
delta_layer_kernel(const float2* __restrict__ x, float2* __restrict__ out) {
    __shared__ alignas(128) float2 sbuf[2][TILE_ROWS * OF2_N];   // 2 x 12 KB

    const int tid = threadIdx.x;              // 0..127 = float2 channel column
    const int seg = blockIdx.x;                // 0..SEGS-1
    const int b   = blockIdx.y;

    const int tile_lo = (seg * NTILES) / SEGS;
    const int tile_hi = ((seg + 1) * NTILES) / SEGS;

    const float2* __restrict__ xb = x + (size_t)b * T_N * F2_N + tid;

    float2 r[9];
    bool warm = false;
    int pbuf = 0;

    for (int tile = tile_lo; tile < tile_hi; ++tile) {
        const int t0 = tile * TILE_ROWS;

        if (tile == 0 || tile == NTILES - 1) {
            // ---- edge tile: generic clamped math, direct global stores ----
            float2* __restrict__ ob = out + (size_t)b * T_N * OF2_N + tid;
            auto LD = [&](int t) -> float2 {
                t = t < 0 ? 0 : (t > T_N - 1 ? T_N - 1 : t);
                return __ldg(xb + (size_t)t * F2_N);
            };
            auto DELTA_AT = [&](int sdx) -> float2 {
                sdx = sdx < 0 ? 0 : (sdx > T_N - 1 ? T_N - 1 : sdx);
                return f2_delta(LD(sdx - 2), LD(sdx - 1), LD(sdx + 1), LD(sdx + 2));
            };
            for (int i = 0; i < TILE_ROWS; ++i) {
                const int t = t0 + i;
                const size_t orow = (size_t)t * OF2_N;
                ob[orow]            = LD(t);
                ob[orow + F2_N]     = DELTA_AT(t);
                ob[orow + 2 * F2_N] =
                    f2_delta(DELTA_AT(t - 2), DELTA_AT(t - 1),
                             DELTA_AT(t + 1), DELTA_AT(t + 2));
            }
            warm = false;
            continue;
        }

        // ---- interior tile ----
        if (!warm) {
            // ring r[j] = x[t0-4+j]; t0 >= 4 for any interior tile
#pragma unroll
            for (int j = 0; j < 9; ++j)
                r[j] = __ldg(xb + (size_t)(t0 - 4 + j) * F2_N);
            warm = true;
        }

        // make sure buffer pbuf (committed 2 tiles ago) has been read out
        if (tid == 0) {
            asm volatile("cp.async.bulk.wait_group.read 1;" ::: "memory");
        }
        __syncthreads();

        float2* sb = sbuf[pbuf];
#pragma unroll
        for (int i = 0; i < TILE_ROWS; ++i) {
            float2* orow = sb + i * OF2_N + tid;
            orow[0]        = r[4];                             // x
            orow[F2_N]     = f2_delta(r[2], r[3], r[5], r[6]); // delta
            float2 dd;
            dd.x = dd9(r[0].x, r[1].x, r[2].x, r[3].x, r[4].x,
                       r[5].x, r[6].x, r[7].x, r[8].x);
            dd.y = dd9(r[0].y, r[1].y, r[2].y, r[3].y, r[4].y,
                       r[5].y, r[6].y, r[7].y, r[8].y);
            orow[2 * F2_N] = dd;                               // double delta

            // shift EVERY row so the ring carries into the next tile;
            // clamp prefetch (only affects rows handled by the edge tile)
#pragma unroll
            for (int j = 0; j < 8; ++j) r[j] = r[j + 1];
            int pf = t0 + 5 + i;
            if (pf > T_N - 1) pf = T_N - 1;
            r[8] = __ldg(xb + (size_t)pf * F2_N);
        }
        __syncthreads();

        if (tid == 0) {
            asm volatile("fence.proxy.async.shared::cta;" ::: "memory");
            float2* dst = out + ((size_t)b * T_N + t0) * OF2_N;
            asm volatile(
                "cp.async.bulk.global.shared::cta.bulk_group [%0], [%1], %2;"
                :: "l"(dst), "r"(smem_u32(sb)), "r"((uint32_t)TBYTES) : "memory");
            asm volatile("cp.async.bulk.commit_group;" ::: "memory");
        }
        pbuf ^= 1;
    }

    // release smem before exit (writes drain after CTA exit)
    if (tid == 0) {
        asm volatile("cp.async.bulk.wait_group.read 0;" ::: "memory");
    }
}

extern "C" void kernel_launch(void* const* d_in, const int* in_sizes, int n_in,
                              void* d_out, int out_size) {
    const float2* x = (const float2*)d_in[0];
    float2* out     = (float2*)d_out;
    // d_in[1] = window (always 2) — baked in.

    dim3 block(128, 1);
    dim3 grid(SEGS, B_N);   // (41, 32) = 1312 blocks ≈ one full wave at 9/SM
    delta_layer_kernel<<<grid, block>>>(x, out);
}

// round 17
// speedup vs baseline: 1.2202x; 1.2202x over previous
#include <cuda_runtime.h>
#include <cstdint>

// delta_layer: out[b,t,:] = [ x, delta(x), delta(delta(x)) ]
// delta(y)[t] = 0.5*(y[c(t+1)]-y[c(t-1)]) + 0.25*(y[c(t+2)]-y[c(t-2)]), c = clamp [0,T-1]
// Shapes fixed: B=32, T=4096, D=256, window=2.
//
// FINAL (= Round-9 champion, 84.1us total / 79.1us kernel, 6.03 TB/s HBM).
// Design-space findings on sm_103a for this 1:3 R/W streaming op:
//   - reads: per-thread 9-deep float2 register ring via __ldg; read path is
//     never the binding constraint (occupancy 44-89% and MLP 1-4 both flat)
//   - writes: staging 8 output rows in 24KB smem and issuing ONE 24KB
//     cp.async.bulk store is worth ~15% (long same-direction DRAM bursts
//     beat interleaved per-warp STG sectors)
//   - L_N=8 / 9 blocks/SM is the optimum: L=4 (16/SM) and L=16 (3/SM) both
//     slower; chaining, split epilogues, L2 policy hints, persistence all
//     flat or negative. DRAM busy pins at ~76% = controller mixed-stream
//     ceiling (~6 TB/s effective).
// Interior rows use the fused 9-tap double-delta:
//   dd(t) = 0.0625(x[t-4]+x[t+4]) + 0.25(x[t-3]+x[t+3]) + 0.25(x[t-2]+x[t+2])
//         - 0.25(x[t-1]+x[t+1]) - 0.625 x[t]

#define B_N 32
#define T_N 4096
#define F2_N 128            // float2 per input row (256 floats)
#define OF2_N 384           // float2 per output row (768 floats)
#define L_N 8               // rows per tile
#define CHUNKS (T_N / L_N)  // 512
#define OUT_BYTES (L_N * OF2_N * 8)   // 24576

__device__ __forceinline__ uint32_t smem_u32(const void* p) {
    uint32_t a;
    asm("{ .reg .u64 t; cvta.to.shared.u64 t, %1; cvt.u32.u64 %0, t; }"
        : "=r"(a) : "l"(p));
    return a;
}

__device__ __forceinline__ float2 f2_delta(float2 m2, float2 m1, float2 p1, float2 p2) {
    float2 r;
    r.x = 0.5f * (p1.x - m1.x) + 0.25f * (p2.x - m2.x);
    r.y = 0.5f * (p1.y - m1.y) + 0.25f * (p2.y - m2.y);
    return r;
}

__device__ __forceinline__ float dd9(float a0, float a1, float a2, float a3, float a4,
                                     float a5, float a6, float a7, float a8) {
    return 0.0625f * (a0 + a8) + 0.25f * (a1 + a7) + 0.25f * (a2 + a6)
         - 0.25f * (a3 + a5) - 0.625f * a4;
}

__global__ void __launch_bounds__(128, 9)
delta_layer_kernel(const float2* __restrict__ x, float2* __restrict__ out) {
    __shared__ alignas(128) float2 s_out[L_N * OF2_N];   // 24 KB output staging

    const int tid   = threadIdx.x;           // 0..127 = float2 channel column
    const int chunk = blockIdx.x;             // 0..511
    const int b     = blockIdx.y;
    const int t0    = chunk * L_N;

    const float2* __restrict__ xb = x + (size_t)b * T_N * F2_N + tid;

    if (chunk != 0 && chunk != CHUNKS - 1) {
        // ---- interior: __ldg register ring -> smem tile -> ONE bulk store ----
        // ring r[j] = x[t0-4+j], all in-bounds for interior chunks
        float2 r[9];
#pragma unroll
        for (int j = 0; j < 9; ++j)
            r[j] = __ldg(xb + (size_t)(t0 - 4 + j) * F2_N);

#pragma unroll
        for (int i = 0; i < L_N; ++i) {
            float2* orow = s_out + i * OF2_N + tid;
            orow[0]        = r[4];                             // x
            orow[F2_N]     = f2_delta(r[2], r[3], r[5], r[6]); // delta
            float2 dd;
            dd.x = dd9(r[0].x, r[1].x, r[2].x, r[3].x, r[4].x, r[5].x, r[6].x, r[7].x, r[8].x);
            dd.y = dd9(r[0].y, r[1].y, r[2].y, r[3].y, r[4].y, r[5].y, r[6].y, r[7].y, r[8].y);
            orow[2 * F2_N] = dd;                               // double delta

            if (i < L_N - 1) {
#pragma unroll
                for (int j = 0; j < 8; ++j) r[j] = r[j + 1];
                // max index: t0+12 <= 4092 < T for interior chunks
                r[8] = __ldg(xb + (size_t)(t0 + 5 + i) * F2_N);
            }
        }
        __syncthreads();

        if (tid == 0) {
            asm volatile("fence.proxy.async.shared::cta;" ::: "memory");
            float2* dst = out + ((size_t)b * T_N + t0) * OF2_N;
            asm volatile(
                "cp.async.bulk.global.shared::cta.bulk_group [%0], [%1], %2;"
                :: "l"(dst), "r"(smem_u32(s_out)), "r"((uint32_t)OUT_BYTES) : "memory");
            asm volatile("cp.async.bulk.commit_group;" ::: "memory");
            asm volatile("cp.async.bulk.wait_group 0;" ::: "memory");
        }
    } else {
        // ---- edge path: generic clamped math, direct global stores ----
        float2* __restrict__ ob = out + (size_t)b * T_N * OF2_N + tid;

        auto LD = [&](int t) -> float2 {
            t = t < 0 ? 0 : (t > T_N - 1 ? T_N - 1 : t);
            return __ldg(xb + (size_t)t * F2_N);
        };
        auto DELTA_AT = [&](int sdx) -> float2 {
            sdx = sdx < 0 ? 0 : (sdx > T_N - 1 ? T_N - 1 : sdx);
            return f2_delta(LD(sdx - 2), LD(sdx - 1), LD(sdx + 1), LD(sdx + 2));
        };

        for (int i = 0; i < L_N; ++i) {
            const int t = t0 + i;
            const size_t orow = (size_t)t * OF2_N;
            ob[orow]            = LD(t);
            ob[orow + F2_N]     = DELTA_AT(t);
            ob[orow + 2 * F2_N] =
                f2_delta(DELTA_AT(t - 2), DELTA_AT(t - 1), DELTA_AT(t + 1), DELTA_AT(t + 2));
        }
    }
}

extern "C" void kernel_launch(void* const* d_in, const int* in_sizes, int n_in,
                              void* d_out, int out_size) {
    const float2* x = (const float2*)d_in[0];
    float2* out     = (float2*)d_out;
    // d_in[1] = window (always 2) — baked in.

    dim3 block(128, 1);
    dim3 grid(CHUNKS, B_N);   // (512, 32) = 16384 blocks
    delta_layer_kernel<<<grid, block>>>(x, out);
}